// round 6
// baseline (speedup 1.0000x reference)
#include <cuda_runtime.h>
#include <cuda_bf16.h>

#define B_    64
#define L_    16384
#define D_    64
#define KSEL  256
#define TILE  128
#define NT    4                      // tiles per CTA (double-buffered)
#define ROWW  68
#define NBINS 4096
#define CAP   2048

__device__ float g_sim[B_ * L_];
__device__ unsigned g_hist[B_ * NBINS];   // zero-init; kernel B re-zeroes

__device__ __forceinline__ unsigned f2u(float f) {
    unsigned b = __float_as_uint(f);
    return (b & 0x80000000u) ? ~b : (b | 0x80000000u);
}
__device__ __forceinline__ float u2f(unsigned u) {
    unsigned b = (u & 0x80000000u) ? (u & 0x7FFFFFFFu) : ~u;
    return __uint_as_float(b);
}

// ---------------------------------------------------------------------------
// Kernel A: sims + per-batch 12-bit histogram. 4 tiles/CTA, 2-stage pipeline.
// ---------------------------------------------------------------------------
__global__ void __launch_bounds__(TILE) sim_kernel(
    const float* __restrict__ q,
    const float* __restrict__ keys,
    const float* __restrict__ gp)
{
    extern __shared__ __align__(16) float tile[];   // [2][TILE*ROWW]
    __shared__ __align__(16) float4 qsm[D_ / 4];

    const int b   = blockIdx.y;
    const int t0  = blockIdx.x * (TILE * NT);
    const int tid = threadIdx.x;

    if (tid < D_ / 4)
        qsm[tid] = reinterpret_cast<const float4*>(q + b * D_)[tid];

    const float4* kbase = reinterpret_cast<const float4*>(
        keys + (size_t)b * L_ * D_ + (size_t)t0 * D_);

    auto issue = [&](int tt, int buf) {
        const float4* src = kbase + tt * (TILE * 16);
        float* dstbase = tile + buf * (TILE * ROWW);
#pragma unroll
        for (int j = 0; j < 16; j++) {
            int f = j * TILE + tid;
            int l = f >> 4;
            int c = f & 15;
            unsigned dst = (unsigned)__cvta_generic_to_shared(
                &dstbase[l * ROWW + c * 4]);
            asm volatile("cp.async.cg.shared.global [%0], [%1], 16;\n"
                         :: "r"(dst), "l"(src + f));
        }
        asm volatile("cp.async.commit_group;\n");
    };

    issue(0, 0);

    __syncthreads();   // qsm visible
    float qq = 0.f;
#pragma unroll
    for (int i = 0; i < D_ / 4; i++) {
        float4 t = qsm[i];
        qq += t.x * t.x + t.y * t.y + t.z * t.z + t.w * t.w;
    }
    const float rq = gp[0] * rsqrtf(qq);

#pragma unroll
    for (int t = 0; t < NT; t++) {
        if (t + 1 < NT) {
            issue(t + 1, (t + 1) & 1);
            asm volatile("cp.async.wait_group 1;\n");
        } else {
            asm volatile("cp.async.wait_group 0;\n");
        }
        __syncthreads();

        const float* tb = tile + (t & 1) * (TILE * ROWW);
        float dot = 0.f, kk = 0.f;
#pragma unroll
        for (int i = 0; i < 16; i++) {
            float4 kv = *reinterpret_cast<const float4*>(&tb[tid * ROWW + i * 4]);
            float4 qv = qsm[i];
            dot += qv.x * kv.x + qv.y * kv.y + qv.z * kv.z + qv.w * kv.w;
            kk  += kv.x * kv.x + kv.y * kv.y + kv.z * kv.z + kv.w * kv.w;
        }
        float sim = dot * rq * rsqrtf(kk);
        g_sim[b * L_ + t0 + t * TILE + tid] = sim;
        atomicAdd(&g_hist[b * NBINS + (f2u(sim) >> 20)], 1u);

        __syncthreads();
    }
}

// ---------------------------------------------------------------------------
// Kernel B: per-batch threshold (register suffix scan) + collect +
// parallel vectorized rank + softmax + gather. One CTA/batch, 1024 threads.
// ---------------------------------------------------------------------------
__global__ void __launch_bounds__(1024) topk_kernel(
    const float* __restrict__ values,
    float* __restrict__ out)
{
    __shared__ __align__(16) unsigned long long cand[CAP];  // 16 KB
    __shared__ int s_rank[CAP];                             // 8 KB
    __shared__ unsigned long long s_key[KSEL];              // 2 KB
    __shared__ float s_e[KSEL];
    __shared__ float s_sum;
    __shared__ int   s_n;
    __shared__ unsigned s_lo;
    __shared__ unsigned s_wtot[32], s_wabove[32];

    const int b    = blockIdx.x;
    const int tid  = threadIdx.x;
    const int lane = tid & 31;
    const int warp = tid >> 5;

    // --- 1. histogram: 4 bins/thread in registers; re-zero global copy ---
    uint4 h = reinterpret_cast<const uint4*>(g_hist + b * NBINS)[tid];
    reinterpret_cast<uint4*>(g_hist + b * NBINS)[tid] = make_uint4(0, 0, 0, 0);
    unsigned sum4 = h.x + h.y + h.z + h.w;

    unsigned suf = sum4;
#pragma unroll
    for (int o = 1; o < 32; o <<= 1) {
        unsigned t = __shfl_down_sync(0xFFFFFFFFu, suf, o);
        if (lane + o < 32) suf += t;
    }
    if (lane == 0) s_wtot[warp] = suf;
    if (tid == 0) s_n = 0;
    __syncthreads();

    if (warp == 0) {
        unsigned wt = s_wtot[lane];
        unsigned wsuf = wt;
#pragma unroll
        for (int o = 1; o < 32; o <<= 1) {
            unsigned t = __shfl_down_sync(0xFFFFFFFFu, wsuf, o);
            if (lane + o < 32) wsuf += t;
        }
        s_wabove[lane] = wsuf - wt;
    }
    __syncthreads();

    unsigned above = s_wabove[warp] + (suf - sum4);
    if (above < KSEL && above + sum4 >= KSEL) {
        unsigned hh[4] = {h.x, h.y, h.z, h.w};
        unsigned acc = above;
        int bin = 4 * tid;
        for (int j = 3; j >= 0; j--) {
            if (acc + hh[j] >= KSEL) { bin = 4 * tid + j; break; }
            acc += hh[j];
        }
        s_lo = ((unsigned)bin) << 20;
    }
    __syncthreads();
    const unsigned lo = s_lo;

    // --- 2. collect candidates >= threshold (hoisted loads, MLP=4) ---
    const float4* simrow4 = reinterpret_cast<const float4*>(g_sim + b * L_);
    float4 sv[4];
#pragma unroll
    for (int r = 0; r < 4; r++)
        sv[r] = simrow4[r * 1024 + tid];

#pragma unroll
    for (int r = 0; r < 4; r++) {
        unsigned u4[4] = {f2u(sv[r].x), f2u(sv[r].y), f2u(sv[r].z), f2u(sv[r].w)};
#pragma unroll
        for (int c = 0; c < 4; c++) {
            bool take = (u4[c] >= lo);
            unsigned m = __ballot_sync(0xFFFFFFFFu, take);
            if (m) {
                int leader = __ffs(m) - 1;
                int basepos = 0;
                if (lane == leader)
                    basepos = atomicAdd(&s_n, __popc(m));
                basepos = __shfl_sync(0xFFFFFFFFu, basepos, leader);
                if (take) {
                    int p = basepos + __popc(m & ((1u << lane) - 1));
                    int i = (r * 1024 + tid) * 4 + c;
                    if (p < CAP - 2)
                        cand[p] = ((unsigned long long)u4[c] << 32) |
                                  (unsigned)(~i);
                }
            }
        }
    }
    __syncthreads();

    int n = s_n; if (n > CAP - 2) n = CAP - 2;

    // --- 3. parallel vectorized rank (desc value, asc index) ---
    // thread (i mod 256, quarter) scans a quarter of j-pairs via LDS.128
    if (tid == 0) { cand[n] = 0ull; cand[n + 1] = 0ull; }  // pad for pair load
    for (int i = tid; i < n; i += 1024) s_rank[i] = 0;
    __syncthreads();

    {
        const int npairs = (n + 1) >> 1;
        const int npq    = (npairs + 3) >> 2;
        const int quart  = tid >> 8;           // 0..3
        const int i0     = tid & 255;
        const int jp0    = quart * npq;
        const int jp1    = (jp0 + npq < npairs) ? jp0 + npq : npairs;
        const ulonglong2* cp = reinterpret_cast<const ulonglong2*>(cand);

        for (int i = i0; i < n; i += 256) {
            unsigned long long me = cand[i];
            int r = 0;
            for (int jp = jp0; jp < jp1; jp++) {
                ulonglong2 p = cp[jp];
                r += (p.x > me) + (p.y > me);
            }
            if (r) atomicAdd(&s_rank[i], r);
        }
    }
    __syncthreads();

    for (int i = tid; i < n; i += 1024) {
        int r = s_rank[i];
        if (r < KSEL) s_key[r] = cand[i];
    }
    __syncthreads();

    // --- 4. softmax over top-256 + gather + output ---
    float maxs = u2f((unsigned)(s_key[0] >> 32));
    float e = 0.f;
    if (tid < KSEL) {
        e = expf(u2f((unsigned)(s_key[tid] >> 32)) - maxs);
        s_e[tid] = e;
    }
    __syncthreads();
    if (tid < 32) {
        float acc = 0.f;
#pragma unroll
        for (int j = 0; j < KSEL / 32; j++) acc += s_e[tid + j * 32];
#pragma unroll
        for (int o = 16; o > 0; o >>= 1)
            acc += __shfl_xor_sync(0xFFFFFFFFu, acc, o);
        if (tid == 0) s_sum = acc;
    }
    __syncthreads();
    if (tid < KSEL) {
        int idx = (int)(~(unsigned)s_key[tid]);
        out[b * KSEL + tid]             = values[b * L_ + idx];   // values_sel
        out[B_ * KSEL + b * KSEL + tid] = e / s_sum;              // weights
    }
}

// ---------------------------------------------------------------------------
extern "C" void kernel_launch(void* const* d_in, const int* in_sizes, int n_in,
                              void* d_out, int out_size)
{
    const float* q      = (const float*)d_in[0];
    const float* keys   = (const float*)d_in[1];
    const float* values = (const float*)d_in[2];
    const float* g      = (const float*)d_in[3];
    float* out = (float*)d_out;

    (void)in_sizes; (void)n_in; (void)out_size;

    const int smemA = 2 * TILE * ROWW * 4;   // 69632 B
    cudaFuncSetAttribute(sim_kernel,
                         cudaFuncAttributeMaxDynamicSharedMemorySize, smemA);
    dim3 gridA(L_ / (TILE * NT), B_);
    sim_kernel<<<gridA, TILE, smemA>>>(q, keys, g);

    topk_kernel<<<B_, 1024>>>(values, out);
}

// round 8
// speedup vs baseline: 1.1094x; 1.1094x over previous
#include <cuda_runtime.h>
#include <cuda.h>
#include <cuda_bf16.h>

#define B_    64
#define L_    16384
#define D_    64
#define KSEL  256
#define TILE  128
#define NT    4
#define ROWW  68
#define NBINS 4096
#define CAP   2048
#define TILE_BYTES (TILE * D_ * 4)   // 32768

__device__ float g_sim[B_ * L_];
__device__ unsigned g_hist[B_ * NBINS];          // zero-init; B re-zeroes
__device__ int g_cnt[B_];                        // zero-init; B re-zeroes
__device__ unsigned long long g_cand[B_ * CAP];
__device__ unsigned long long g_key[B_ * KSEL];  // ranks 0..255 rewritten each launch

__device__ __forceinline__ unsigned f2u(float f) {
    unsigned b = __float_as_uint(f);
    return (b & 0x80000000u) ? ~b : (b | 0x80000000u);
}
__device__ __forceinline__ float u2f(unsigned u) {
    unsigned b = (u & 0x80000000u) ? (u & 0x7FFFFFFFu) : ~u;
    return __uint_as_float(b);
}

// ---- mbarrier / TMA helpers -----------------------------------------------
__device__ __forceinline__ unsigned sm_u32(const void* p) {
    return (unsigned)__cvta_generic_to_shared(p);
}
__device__ __forceinline__ void mbar_init(void* m, unsigned cnt) {
    asm volatile("mbarrier.init.shared.b64 [%0], %1;"
                 :: "r"(sm_u32(m)), "r"(cnt) : "memory");
}
__device__ __forceinline__ void mbar_expect_tx(void* m, unsigned bytes) {
    asm volatile("mbarrier.arrive.expect_tx.shared.b64 _, [%0], %1;"
                 :: "r"(sm_u32(m)), "r"(bytes) : "memory");
}
__device__ __forceinline__ void tma_load3d(void* dst, const CUtensorMap* tm,
                                           int x, int y, int z, void* m) {
    asm volatile(
        "cp.async.bulk.tensor.3d.shared::cta.global.tile.mbarrier::complete_tx::bytes "
        "[%0], [%1, {%2, %3, %4}], [%5];"
        :: "r"(sm_u32(dst)), "l"(tm), "r"(x), "r"(y), "r"(z), "r"(sm_u32(m))
        : "memory");
}
__device__ __forceinline__ void mbar_wait(void* m, unsigned parity) {
    asm volatile(
        "{\n\t.reg .pred P;\n\t"
        "W%=:\n\t"
        "mbarrier.try_wait.parity.acquire.cta.shared::cta.b64 P, [%0], %1, 0x989680;\n\t"
        "@P bra D%=;\n\t"
        "bra W%=;\n\t"
        "D%=:\n\t}"
        :: "r"(sm_u32(m)), "r"(parity) : "memory");
}

// ---------------------------------------------------------------------------
// Kernel A (TMA + SW128): sims + per-batch histogram. Fixed accumulation
// order c=0..15 (identical FP tree to the proven cp.async kernel); the
// swizzle only changes ADDRESSES, never the chunk pairing or order.
// Layout: keys viewed as [32 floats][2L subrows][B]; key t = subrows 2t,2t+1.
// ---------------------------------------------------------------------------
__global__ void __launch_bounds__(TILE) sim_tma_kernel(
    const __grid_constant__ CUtensorMap tmap,
    const float* __restrict__ q,
    const float* __restrict__ gp)
{
    extern __shared__ __align__(1024) float smem[];
    // [0,32KB) buf0  [32KB,64KB) buf1  then qsm (64 floats) then mbars
    float4* qsm = reinterpret_cast<float4*>(smem + 2 * TILE * D_);
    unsigned long long* mbar =
        reinterpret_cast<unsigned long long*>(smem + 2 * TILE * D_ + 64);

    const int b   = blockIdx.y;
    const int t0  = blockIdx.x * (TILE * NT);
    const int tid = threadIdx.x;

    if (tid < D_ / 4)
        qsm[tid] = reinterpret_cast<const float4*>(q + b * D_)[tid];
    if (tid == 0) { mbar_init(&mbar[0], 1); mbar_init(&mbar[1], 1); }
    __syncthreads();

    if (tid == 0) {
        mbar_expect_tx(&mbar[0], TILE_BYTES);
        tma_load3d(smem, &tmap, 0, 2 * t0, b, &mbar[0]);
    }

    float qq = 0.f;
#pragma unroll
    for (int i = 0; i < D_ / 4; i++) {
        float4 t = qsm[i];
        qq += t.x * t.x + t.y * t.y + t.z * t.z + t.w * t.w;
    }
    const float rq = gp[0] * rsqrtf(qq);

#pragma unroll
    for (int t = 0; t < NT; t++) {
        if (t + 1 < NT && tid == 0) {
            int nb = (t + 1) & 1;
            mbar_expect_tx(&mbar[nb], TILE_BYTES);
            tma_load3d(smem + nb * (TILE * D_), &tmap,
                       0, 2 * (t0 + (t + 1) * TILE), b, &mbar[nb]);
        }
        mbar_wait(&mbar[t & 1], (t >> 1) & 1);

        const float* base = smem + (t & 1) * (TILE * D_);
        float dot = 0.f, kk = 0.f;
#pragma unroll
        for (int i = 0; i < 16; i++) {
            int r   = 2 * tid + (i >> 3);        // subrow of chunk i
            int c16 = (i & 7) ^ (r & 7);          // SW128 swizzled 16B slot
            float4 kv = *reinterpret_cast<const float4*>(base + r * 32 + c16 * 4);
            float4 qv = qsm[i];
            dot += qv.x * kv.x + qv.y * kv.y + qv.z * kv.z + qv.w * kv.w;
            kk  += kv.x * kv.x + kv.y * kv.y + kv.z * kv.z + kv.w * kv.w;
        }
        float sim = dot * rq * rsqrtf(kk);
        g_sim[b * L_ + t0 + t * TILE + tid] = sim;
        atomicAdd(&g_hist[b * NBINS + (f2u(sim) >> 20)], 1u);

        __syncthreads();   // buffer free before reuse at t+2
    }
}

// ---------------------------------------------------------------------------
// Kernel A fallback (cp.async, proven R6 source) — if tensormap unavailable.
// ---------------------------------------------------------------------------
__global__ void __launch_bounds__(TILE) sim_kernel(
    const float* __restrict__ q,
    const float* __restrict__ keys,
    const float* __restrict__ gp)
{
    extern __shared__ __align__(16) float tile[];   // [2][TILE*ROWW]
    __shared__ __align__(16) float4 qsm[D_ / 4];

    const int b   = blockIdx.y;
    const int t0  = blockIdx.x * (TILE * NT);
    const int tid = threadIdx.x;

    if (tid < D_ / 4)
        qsm[tid] = reinterpret_cast<const float4*>(q + b * D_)[tid];

    const float4* kbase = reinterpret_cast<const float4*>(
        keys + (size_t)b * L_ * D_ + (size_t)t0 * D_);

    auto issue = [&](int tt, int buf) {
        const float4* src = kbase + tt * (TILE * 16);
        float* dstbase = tile + buf * (TILE * ROWW);
#pragma unroll
        for (int j = 0; j < 16; j++) {
            int f = j * TILE + tid;
            int l = f >> 4;
            int c = f & 15;
            unsigned dst = sm_u32(&dstbase[l * ROWW + c * 4]);
            asm volatile("cp.async.cg.shared.global [%0], [%1], 16;\n"
                         :: "r"(dst), "l"(src + f));
        }
        asm volatile("cp.async.commit_group;\n");
    };

    issue(0, 0);
    __syncthreads();
    float qq = 0.f;
#pragma unroll
    for (int i = 0; i < D_ / 4; i++) {
        float4 t = qsm[i];
        qq += t.x * t.x + t.y * t.y + t.z * t.z + t.w * t.w;
    }
    const float rq = gp[0] * rsqrtf(qq);

#pragma unroll
    for (int t = 0; t < NT; t++) {
        if (t + 1 < NT) {
            issue(t + 1, (t + 1) & 1);
            asm volatile("cp.async.wait_group 1;\n");
        } else {
            asm volatile("cp.async.wait_group 0;\n");
        }
        __syncthreads();
        const float* tb = tile + (t & 1) * (TILE * ROWW);
        float dot = 0.f, kk = 0.f;
#pragma unroll
        for (int i = 0; i < 16; i++) {
            float4 kv = *reinterpret_cast<const float4*>(&tb[tid * ROWW + i * 4]);
            float4 qv = qsm[i];
            dot += qv.x * kv.x + qv.y * kv.y + qv.z * kv.z + qv.w * kv.w;
            kk  += kv.x * kv.x + kv.y * kv.y + kv.z * kv.z + kv.w * kv.w;
        }
        float sim = dot * rq * rsqrtf(kk);
        g_sim[b * L_ + t0 + t * TILE + tid] = sim;
        atomicAdd(&g_hist[b * NBINS + (f2u(sim) >> 20)], 1u);
        __syncthreads();
    }
}

// ---------------------------------------------------------------------------
// Kernel B: cluster pair (2 CTAs/batch). Threshold redundant; collect split;
// rank split over i; softmax redundant; outputs split.
// ---------------------------------------------------------------------------
__global__ void __launch_bounds__(1024) __cluster_dims__(2, 1, 1)
topk_kernel(const float* __restrict__ values, float* __restrict__ out)
{
    __shared__ __align__(16) unsigned long long cand[CAP];
    __shared__ int s_rank[CAP];
    __shared__ unsigned long long s_key[KSEL];
    __shared__ float s_e[KSEL];
    __shared__ float s_sum;
    __shared__ int   s_ln, s_base;
    __shared__ unsigned s_lo;
    __shared__ unsigned s_wtot[32], s_wabove[32];

    const int b    = blockIdx.x >> 1;
    const int half = blockIdx.x & 1;
    const int tid  = threadIdx.x;
    const int lane = tid & 31;
    const int warp = tid >> 5;

    // --- 1. threshold from histogram (both CTAs, redundant) ---
    uint4 h = reinterpret_cast<const uint4*>(g_hist + b * NBINS)[tid];
    unsigned sum4 = h.x + h.y + h.z + h.w;
    unsigned suf = sum4;
#pragma unroll
    for (int o = 1; o < 32; o <<= 1) {
        unsigned t = __shfl_down_sync(0xFFFFFFFFu, suf, o);
        if (lane + o < 32) suf += t;
    }
    if (lane == 0) s_wtot[warp] = suf;
    if (tid == 0) s_ln = 0;
    __syncthreads();
    if (warp == 0) {
        unsigned wt = s_wtot[lane];
        unsigned wsuf = wt;
#pragma unroll
        for (int o = 1; o < 32; o <<= 1) {
            unsigned t = __shfl_down_sync(0xFFFFFFFFu, wsuf, o);
            if (lane + o < 32) wsuf += t;
        }
        s_wabove[lane] = wsuf - wt;
    }
    __syncthreads();
    unsigned above = s_wabove[warp] + (suf - sum4);
    if (above < KSEL && above + sum4 >= KSEL) {
        unsigned hh[4] = {h.x, h.y, h.z, h.w};
        unsigned acc = above;
        int bin = 4 * tid;
        for (int j = 3; j >= 0; j--) {
            if (acc + hh[j] >= KSEL) { bin = 4 * tid + j; break; }
            acc += hh[j];
        }
        s_lo = ((unsigned)bin) << 20;
    }
    __syncthreads();
    const unsigned lo = s_lo;

    // --- 2. collect this CTA's half of L into local smem list ---
    const float4* simrow4 = reinterpret_cast<const float4*>(g_sim + b * L_);
    float4 sv[2];
#pragma unroll
    for (int r = 0; r < 2; r++)
        sv[r] = simrow4[half * 2048 + r * 1024 + tid];
#pragma unroll
    for (int r = 0; r < 2; r++) {
        unsigned u4[4] = {f2u(sv[r].x), f2u(sv[r].y), f2u(sv[r].z), f2u(sv[r].w)};
#pragma unroll
        for (int c = 0; c < 4; c++) {
            bool take = (u4[c] >= lo);
            unsigned m = __ballot_sync(0xFFFFFFFFu, take);
            if (m) {
                int leader = __ffs(m) - 1;
                int basepos = 0;
                if (lane == leader)
                    basepos = atomicAdd(&s_ln, __popc(m));
                basepos = __shfl_sync(0xFFFFFFFFu, basepos, leader);
                if (take) {
                    int p = basepos + __popc(m & ((1u << lane) - 1));
                    int i = (half * 2048 + r * 1024 + tid) * 4 + c;
                    if (p < CAP)
                        cand[p] = ((unsigned long long)u4[c] << 32) |
                                  (unsigned)(~i);
                }
            }
        }
    }
    __syncthreads();

    // bulk append to global per-batch list (one ATOMG per CTA)
    int ln = s_ln; if (ln > CAP) ln = CAP;
    if (tid == 0) s_base = atomicAdd(&g_cnt[b], ln);
    __syncthreads();
    int gbase = s_base;
    for (int i = tid; i < ln; i += 1024) {
        int p = gbase + i;
        if (p < CAP) g_cand[b * CAP + p] = cand[i];
    }

    __threadfence();
    asm volatile("barrier.cluster.arrive.aligned;" ::: "memory");
    asm volatile("barrier.cluster.wait.aligned;"   ::: "memory");

    // rank-0 CTA re-zeroes the histogram for the next replay
    if (half == 0)
        reinterpret_cast<uint4*>(g_hist + b * NBINS)[tid] = make_uint4(0, 0, 0, 0);

    // --- 3. full list; rank this CTA's interleaved i's ---
    int n = g_cnt[b]; if (n > CAP - 2) n = CAP - 2;
    for (int i = tid; i < n; i += 1024) cand[i] = g_cand[b * CAP + i];
    for (int i = tid; i < n; i += 1024) s_rank[i] = 0;
    if (tid == 0) { cand[n] = 0ull; cand[n + 1] = 0ull; }
    __syncthreads();

    {
        const int npairs = (n + 1) >> 1;
        const int npq    = (npairs + 3) >> 2;
        const int quart  = tid >> 8;
        const int jp0    = quart * npq;
        const int jp1    = (jp0 + npq < npairs) ? jp0 + npq : npairs;
        const ulonglong2* cp = reinterpret_cast<const ulonglong2*>(cand);

        for (int ii = tid & 255; 2 * ii + half < n; ii += 256) {
            int i = 2 * ii + half;
            unsigned long long me = cand[i];
            int r = 0;
            for (int jp = jp0; jp < jp1; jp++) {
                ulonglong2 p = cp[jp];
                r += (p.x > me) + (p.y > me);
            }
            if (r) atomicAdd(&s_rank[i], r);
        }
    }
    __syncthreads();

    for (int ii = tid & 255; 2 * ii + half < n; ii += 256) {
        if (tid < 256) {
            int i = 2 * ii + half;
            int r = s_rank[i];
            if (r < KSEL) g_key[b * KSEL + r] = cand[i];
        }
    }

    __threadfence();
    asm volatile("barrier.cluster.arrive.aligned;" ::: "memory");
    asm volatile("barrier.cluster.wait.aligned;"   ::: "memory");

    if (half == 0 && tid == 0) g_cnt[b] = 0;   // reset for next replay

    // --- 4. softmax (redundant) + split output ---
    if (tid < KSEL) s_key[tid] = g_key[b * KSEL + tid];
    __syncthreads();
    float maxs = u2f((unsigned)(s_key[0] >> 32));
    if (tid < KSEL)
        s_e[tid] = expf(u2f((unsigned)(s_key[tid] >> 32)) - maxs);
    __syncthreads();
    if (tid < 32) {
        float acc = 0.f;
#pragma unroll
        for (int j = 0; j < KSEL / 32; j++) acc += s_e[tid + j * 32];
#pragma unroll
        for (int o = 16; o > 0; o >>= 1)
            acc += __shfl_xor_sync(0xFFFFFFFFu, acc, o);
        if (tid == 0) s_sum = acc;
    }
    __syncthreads();
    if (tid < KSEL / 2) {
        int kidx = half * (KSEL / 2) + tid;
        int idx  = (int)(~(unsigned)s_key[kidx]);
        out[b * KSEL + kidx]             = values[b * L_ + idx];
        out[B_ * KSEL + b * KSEL + kidx] = s_e[kidx] / s_sum;
    }
}

// ---------------------------------------------------------------------------
extern "C" void kernel_launch(void* const* d_in, const int* in_sizes, int n_in,
                              void* d_out, int out_size)
{
    const float* q      = (const float*)d_in[0];
    const float* keys   = (const float*)d_in[1];
    const float* values = (const float*)d_in[2];
    const float* g      = (const float*)d_in[3];
    float* out = (float*)d_out;
    (void)in_sizes; (void)n_in; (void)out_size;

    // Tensormap: keys as [32 floats][2L subrows][B], SW128, box {32,256,1}
    typedef CUresult (*EncodeFn)(CUtensorMap*, CUtensorMapDataType, cuuint32_t,
                                 void*, const cuuint64_t*, const cuuint64_t*,
                                 const cuuint32_t*, const cuuint32_t*,
                                 CUtensorMapInterleave, CUtensorMapSwizzle,
                                 CUtensorMapL2promotion, CUtensorMapFloatOOBfill);
    CUtensorMap tmap;
    bool tma_ok = false;
    {
        void* fp = nullptr;
        cudaDriverEntryPointQueryResult qr;
        if (cudaGetDriverEntryPointByVersion("cuTensorMapEncodeTiled", &fp,
                                             12000, cudaEnableDefault, &qr)
                == cudaSuccess && fp) {
            cuuint64_t dims[3]    = {32, (cuuint64_t)2 * L_, B_};
            cuuint64_t strides[2] = {128, (cuuint64_t)L_ * D_ * 4};
            cuuint32_t box[3]     = {32, 2 * TILE, 1};
            cuuint32_t es[3]      = {1, 1, 1};
            EncodeFn fn = (EncodeFn)fp;
            tma_ok = (fn(&tmap, CU_TENSOR_MAP_DATA_TYPE_FLOAT32, 3,
                         (void*)keys, dims, strides, box, es,
                         CU_TENSOR_MAP_INTERLEAVE_NONE,
                         CU_TENSOR_MAP_SWIZZLE_128B,
                         CU_TENSOR_MAP_L2_PROMOTION_L2_128B,
                         CU_TENSOR_MAP_FLOAT_OOB_FILL_NONE) == CUDA_SUCCESS);
        }
    }

    dim3 gridA(L_ / (TILE * NT), B_);
    if (tma_ok) {
        const int smemA = 2 * TILE * D_ * 4 + 256 + 64;   // 65856 B
        cudaFuncSetAttribute(sim_tma_kernel,
                             cudaFuncAttributeMaxDynamicSharedMemorySize, smemA);
        sim_tma_kernel<<<gridA, TILE, smemA>>>(tmap, q, g);
    } else {
        const int smemF = 2 * TILE * ROWW * 4;            // 69632 B
        cudaFuncSetAttribute(sim_kernel,
                             cudaFuncAttributeMaxDynamicSharedMemorySize, smemF);
        sim_kernel<<<gridA, TILE, smemF>>>(q, keys, g);
    }

    topk_kernel<<<2 * B_, 1024>>>(values, out);
}